// round 3
// baseline (speedup 1.0000x reference)
#include <cuda_runtime.h>
#include <stdint.h>

// Quantum 2x2 gate apply on qubit axis TARGET=5 of state (2,)^24 x (4,) f32.
// 256-bit (v8) global loads/stores: unit = 8 floats (32B).
// Target-axis stride = 2^20 floats = 2^17 v8-units.
// Pairs of v8-units: 2^23 total v8-units / 2 = 2^22 pairs, one per thread.

static constexpr int SHIFT = 17;                   // target stride in v8 units
static constexpr long long NPAIRS = 1LL << 22;     // 4,194,304

__device__ __forceinline__ void ldg256(const float* p, uint32_t r[8]) {
    asm volatile("ld.global.v8.b32 {%0,%1,%2,%3,%4,%5,%6,%7}, [%8];"
                 : "=r"(r[0]), "=r"(r[1]), "=r"(r[2]), "=r"(r[3]),
                   "=r"(r[4]), "=r"(r[5]), "=r"(r[6]), "=r"(r[7])
                 : "l"(p));
}

__device__ __forceinline__ void stg256(float* p, const uint32_t r[8]) {
    asm volatile("st.global.v8.b32 [%0], {%1,%2,%3,%4,%5,%6,%7,%8};"
                 :: "l"(p),
                    "r"(r[0]), "r"(r[1]), "r"(r[2]), "r"(r[3]),
                    "r"(r[4]), "r"(r[5]), "r"(r[6]), "r"(r[7]));
}

__global__ __launch_bounds__(256)
void gate_apply_kernel(const float* __restrict__ state,
                       const float* __restrict__ pauli,
                       float* __restrict__ out)
{
    long long v = (long long)blockIdx.x * blockDim.x + threadIdx.x;
    if (v >= NPAIRS) return;

    const float p00 = pauli[0];
    const float p01 = pauli[1];
    const float p10 = pauli[2];
    const float p11 = pauli[3];

    long long low  = v & ((1LL << SHIFT) - 1);
    long long u0   = ((v >> SHIFT) << (SHIFT + 1)) | low;   // v8-unit index, t=0
    long long u1   = u0 + (1LL << SHIFT);                   // t=1

    const float* s0p = state + (u0 << 3);
    const float* s1p = state + (u1 << 3);

    uint32_t a0[8], a1[8];
    ldg256(s0p, a0);
    ldg256(s1p, a1);

    uint32_t o0[8], o1[8];
#pragma unroll
    for (int i = 0; i < 8; i++) {
        float s0 = __uint_as_float(a0[i]);
        float s1 = __uint_as_float(a1[i]);
        o0[i] = __float_as_uint(p00 * s0 + p01 * s1);
        o1[i] = __float_as_uint(p10 * s0 + p11 * s1);
    }

    stg256(out + (u0 << 3), o0);
    stg256(out + (u1 << 3), o1);
}

extern "C" void kernel_launch(void* const* d_in, const int* in_sizes, int n_in,
                              void* d_out, int out_size)
{
    const float* state = (const float*)d_in[0];
    const float* pauli = (const float*)d_in[1];
    float* out = (float*)d_out;

    const int threads = 256;
    const long long blocks = (NPAIRS + threads - 1) / threads;  // 16384
    gate_apply_kernel<<<(unsigned)blocks, threads>>>(state, pauli, out);
}